// round 8
// baseline (speedup 1.0000x reference)
#include <cuda_runtime.h>
#include <cuda_bf16.h>

// DipolePredictorE3NN: per-(b,n) equivariant tensor product + mean over N + tiny MLP.
// feats (1024,4096,8) f32, edge_attr (1024,4096,3) f32 -> out (1024,3) f32.
// One CTA per batch. Per-element mapping n = tid + k*NTHREADS:
//   feats  -> 2x LDG.128 at 32-B lane stride  (8 lines per warp-instr / 32 elems)
//   edge   -> 3x LDG.32  at 12-B lane stride  (3 lines each)
// = ~25 L1 wavefronts per 32 elements (vs 73 in the 4-elem/thread layout),
// pushing the bottleneck from L1tex back to DRAM.

#define BATCH 1024
#define NELEM 4096
#define NTHREADS 256
#define NITER (NELEM / NTHREADS)   // 16

__device__ __forceinline__ float warp_sum(float v) {
    #pragma unroll
    for (int off = 16; off > 0; off >>= 1)
        v += __shfl_xor_sync(0xFFFFFFFFu, v, off);
    return v;
}

__global__ __launch_bounds__(NTHREADS, 8)
void dipole_e3nn_kernel(const float* __restrict__ feats,
                        const float* __restrict__ edge,
                        const float* __restrict__ w_path0,
                        const float* __restrict__ w_path1,
                        const float* __restrict__ W1,
                        const float* __restrict__ b1,
                        const float* __restrict__ W2,
                        const float* __restrict__ b2,
                        float* __restrict__ out)
{
    const int b   = blockIdx.x;
    const int tid = threadIdx.x;

    // sqrt(0.5)/sqrt(3), sqrt(0.5)/sqrt(6)
    const float C01 = 0.40824829046386301636f;
    const float C11 = 0.28867513459481286553f;

    const float w00 = __ldg(w_path0 + 0);
    const float w01 = __ldg(w_path0 + 1);
    const float w02 = __ldg(w_path0 + 2);
    const float w03 = __ldg(w_path0 + 3);
    const float w04 = __ldg(w_path0 + 4);
    const float c11 = C11 * __ldg(w_path1);

    const float4* __restrict__ f4 = (const float4*)(feats + (size_t)b * NELEM * 8);
    const float*  __restrict__ e  = edge + (size_t)b * NELEM * 3;

    float ax = 0.0f, ay = 0.0f, az = 0.0f;

    #pragma unroll 4
    for (int k = 0; k < NITER; k++) {
        const int n = tid + k * NTHREADS;
        const float4 fa = f4[2 * n];      // feats[n][0..3]   (32-B lane stride)
        const float4 fb = f4[2 * n + 1];  // feats[n][4..7]
        const float e0 = e[3 * n + 0];    // 12-B lane stride
        const float e1 = e[3 * n + 1];
        const float e2 = e[3 * n + 2];

        const float s = fa.x * w00 + fa.y * w01 + fa.z * w02
                      + fa.w * w03 + fb.x * w04;
        const float cs = C01 * s;
        const float v0 = fb.y, v1 = fb.z, v2 = fb.w;

        ax += cs * e0 + c11 * (v1 * e2 - v2 * e1);
        ay += cs * e1 + c11 * (v2 * e0 - v0 * e2);
        az += cs * e2 + c11 * (v0 * e1 - v1 * e0);
    }

    // ---- block reduction of (ax, ay, az) ----
    ax = warp_sum(ax);
    ay = warp_sum(ay);
    az = warp_sum(az);

    __shared__ float red[NTHREADS / 32][3];
    __shared__ float g[3];
    __shared__ float outred[4][3];

    const int wid = tid >> 5;
    const int lid = tid & 31;
    if (lid == 0) {
        red[wid][0] = ax;
        red[wid][1] = ay;
        red[wid][2] = az;
    }
    __syncthreads();

    if (tid < 3) {
        float s = 0.0f;
        #pragma unroll
        for (int w = 0; w < NTHREADS / 32; w++) s += red[w][tid];
        g[tid] = s * (1.0f / (float)NELEM);
    }
    __syncthreads();

    // ---- MLP epilogue: h = relu(g @ W1 + b1) ; out = h @ W2 + b2 ----
    if (tid < 128) {
        const int j = tid;
        float h = g[0] * __ldg(W1 + j)
                + g[1] * __ldg(W1 + 128 + j)
                + g[2] * __ldg(W1 + 256 + j)
                + __ldg(b1 + j);
        h = fmaxf(h, 0.0f);

        float p0 = h * __ldg(W2 + 3 * j + 0);
        float p1 = h * __ldg(W2 + 3 * j + 1);
        float p2 = h * __ldg(W2 + 3 * j + 2);

        p0 = warp_sum(p0);
        p1 = warp_sum(p1);
        p2 = warp_sum(p2);

        if (lid == 0) {
            outred[wid][0] = p0;
            outred[wid][1] = p1;
            outred[wid][2] = p2;
        }
    }
    __syncthreads();

    if (tid < 3) {
        float s = outred[0][tid] + outred[1][tid] + outred[2][tid] + outred[3][tid]
                + __ldg(b2 + tid);
        out[b * 3 + tid] = s;
    }
}

extern "C" void kernel_launch(void* const* d_in, const int* in_sizes, int n_in,
                              void* d_out, int out_size) {
    const float* feats   = (const float*)d_in[0];
    const float* edge    = (const float*)d_in[1];
    const float* w_path0 = (const float*)d_in[2];
    const float* w_path1 = (const float*)d_in[3];
    const float* W1      = (const float*)d_in[4];
    const float* b1      = (const float*)d_in[5];
    const float* W2      = (const float*)d_in[6];
    const float* b2      = (const float*)d_in[7];
    float* out = (float*)d_out;

    dipole_e3nn_kernel<<<BATCH, NTHREADS>>>(feats, edge, w_path0, w_path1,
                                            W1, b1, W2, b2, out);
}